// round 6
// baseline (speedup 1.0000x reference)
#include <cuda_runtime.h>

#define NTOK   1024
#define DIM    128
#define BI     16
#define NSPLIT 8
#define JSPAN  (NTOK / NSPLIT)   // 128

typedef unsigned long long ull;

// ---- packed f32x2 helpers (Blackwell) -------------------------------------
__device__ __forceinline__ ull pack2(float x, float y) {
    ull r; asm("mov.b64 %0, {%1, %2};" : "=l"(r) : "f"(x), "f"(y)); return r;
}
__device__ __forceinline__ void unpack2(ull v, float& x, float& y) {
    asm("mov.b64 {%0, %1}, %2;" : "=f"(x), "=f"(y) : "l"(v));
}
__device__ __forceinline__ ull add2(ull a, ull b) {
    ull r; asm("add.rn.f32x2 %0, %1, %2;" : "=l"(r) : "l"(a), "l"(b)); return r;
}
__device__ __forceinline__ ull fma2(ull a, ull b, ull c) {
    ull r; asm("fma.rn.f32x2 %0, %1, %2, %3;" : "=l"(r) : "l"(a), "l"(b), "l"(c)); return r;
}
__device__ __forceinline__ ull relu2(ull a) {
    float x, y; unpack2(a, x, y);
    return pack2(fmaxf(x, 0.f), fmaxf(y, 0.f));
}

// Scratch (__device__ globals: allocation-free rule)
__device__ float Qg[NTOK * DIM];
__device__ float Kg[NTOK * DIM];
__device__ float Vg[NTOK * DIM];
__device__ float Rpart[NSPLIT][NTOK][DIM];
__device__ float Vpart[NSPLIT][NTOK][DIM];
__device__ float Mpart[NSPLIT][NTOK];
__device__ float Spart[NSPLIT][NTOK];

// ---------------------------------------------------------------------------
// Kernel 1: Q/K/V = x @ W + b. grid (256, 3), 128 thr, 4 rows/block.
// thread = 1 row x 4 cols. Big reg budget -> unroll-8 LDG.128 stays in flight.
// ---------------------------------------------------------------------------
__global__ __launch_bounds__(128, 4) void qkv_kernel(
    const float* __restrict__ x,
    const float* __restrict__ Wq, const float* __restrict__ bq,
    const float* __restrict__ Wk, const float* __restrict__ bk,
    const float* __restrict__ Wv, const float* __restrict__ bv)
{
    __shared__ float xs[4 * DIM];
    const int tid = threadIdx.x;
    const int rt = blockIdx.x;
    const int m  = blockIdx.y;
    const float* W = (m == 0) ? Wq : (m == 1) ? Wk : Wv;
    const float* b = (m == 0) ? bq : (m == 1) ? bk : bv;
    float* outp    = (m == 0) ? Qg : (m == 1) ? Kg : Vg;

    ((float4*)xs)[tid] = ((const float4*)(x + rt * 4 * DIM))[tid];  // 512 floats
    __syncthreads();

    const int row = tid >> 5;
    const int c0  = (tid & 31) * 4;
    float4 acc = *(const float4*)(b + c0);
    const float* xr = xs + row * DIM;

#pragma unroll 8
    for (int d = 0; d < DIM; d++) {
        float4 w = *(const float4*)(W + d * DIM + c0);
        float xv = xr[d];
        acc.x += xv * w.x;  acc.y += xv * w.y;
        acc.z += xv * w.z;  acc.w += xv * w.w;
    }
    *(float4*)(outp + (rt * 4 + row) * DIM + c0) = acc;
}

// ---------------------------------------------------------------------------
// Kernel 2: per-(i-tile, j-split) partial attention.  BI=16, JSPAN=128.
// ---------------------------------------------------------------------------
__global__ __launch_bounds__(256) void attn_partial(const float* __restrict__ WA)
{
    __shared__ float esA[2][BI][JSPAN];  // 16 KB (d-half partials -> p buffer)
    __shared__ float Qs[BI * DIM];       // 8 KB (row-major, phase B)
    __shared__ float QsT[DIM * BI];      // 8 KB (transposed, phase A)
    __shared__ ull   WAs2[DIM];          // 1 KB ((wa,wa))

    const int tid = threadIdx.x;
    const int ib0 = blockIdx.x * BI;
    const int sp  = blockIdx.y;
    const int js0 = sp * JSPAN;

    ((float4*)Qs)[tid]       = ((const float4*)(Qg + ib0 * DIM))[tid];
    ((float4*)Qs)[tid + 256] = ((const float4*)(Qg + ib0 * DIM))[tid + 256];
    for (int k = tid; k < BI * DIM; k += 256)
        QsT[(k & 127) * BI + (k >> 7)] = Qg[ib0 * DIM + k];   // coalesced LDG
    if (tid < DIM) { float w = WA[tid]; WAs2[tid] = pack2(w, w); }
    __syncthreads();

    // -------- Phase A: thread = (j, d-half); packed over i-pairs ----------
    {
        const int j  = tid & 127;
        const int dh = tid >> 7;          // 0/1 -> d range [dh*64, dh*64+64)
        ull e2[BI / 2];
#pragma unroll
        for (int p = 0; p < BI / 2; p++) e2[p] = 0ull;
        const float* krow = Kg + (js0 + j) * DIM + dh * 64;

#pragma unroll
        for (int db = 0; db < 64; db += 16) {
            float4 k0 = *(const float4*)(krow + db);
            float4 k1 = *(const float4*)(krow + db + 4);
            float4 k2 = *(const float4*)(krow + db + 8);
            float4 k3 = *(const float4*)(krow + db + 12);
            float kv[16];
            kv[0]=k0.x; kv[1]=k0.y; kv[2]=k0.z; kv[3]=k0.w;
            kv[4]=k1.x; kv[5]=k1.y; kv[6]=k1.z; kv[7]=k1.w;
            kv[8]=k2.x; kv[9]=k2.y; kv[10]=k2.z; kv[11]=k2.w;
            kv[12]=k3.x; kv[13]=k3.y; kv[14]=k3.z; kv[15]=k3.w;
#pragma unroll
            for (int t = 0; t < 16; t++) {
                const int d = dh * 64 + db + t;
                ull kk2 = pack2(kv[t], kv[t]);
                ull wa2 = WAs2[d];                             // LDS.64 bcast
#pragma unroll
                for (int p = 0; p < BI / 2; p++) {
                    ull q2 = *(const ull*)&QsT[d * BI + 2 * p]; // LDS.64 bcast
                    e2[p] = fma2(relu2(add2(q2, kk2)), wa2, e2[p]);
                }
            }
        }
#pragma unroll
        for (int p = 0; p < BI / 2; p++) {
            float ex, ey; unpack2(e2[p], ex, ey);
            esA[dh][2 * p][j]     = ex;
            esA[dh][2 * p + 1][j] = ey;
        }
    }
    __syncthreads();

    // -------- split-local softmax: warp w -> rows 2w, 2w+1 ----------------
    {
        const int w = tid >> 5, lane = tid & 31;
#pragma unroll
        for (int rr = 0; rr < 2; rr++) {
            const int row = w * 2 + rr;
            float mx = -1e30f;
            float ev[4];
#pragma unroll
            for (int q = 0; q < 4; q++) {
                int j = lane + q * 32;
                ev[q] = esA[0][row][j] + esA[1][row][j];
                mx = fmaxf(mx, ev[q]);
            }
#pragma unroll
            for (int o = 16; o > 0; o >>= 1) mx = fmaxf(mx, __shfl_xor_sync(0xffffffffu, mx, o));
            float s = 0.f;
#pragma unroll
            for (int q = 0; q < 4; q++) {
                float v = __expf(ev[q] - mx);
                esA[0][row][lane + q * 32] = v;               // unnormalized p
                s += v;
            }
#pragma unroll
            for (int o = 16; o > 0; o >>= 1) s += __shfl_xor_sync(0xffffffffu, s, o);
            if (lane == 0) {
                Mpart[sp][ib0 + row] = mx;
                Spart[sp][ib0 + row] = s;
            }
        }
    }
    __syncthreads();

    // -------- Phase B: thread = 2 i x 4 d, packed over d-pairs ------------
    const int d0 = (tid & 31) * 4;
    const int ig = tid >> 5;              // warp-uniform
    const int i0 = ig, i1 = ig + 8;
    const ull q0lo = *(const ull*)(Qs + i0 * DIM + d0);
    const ull q0hi = *(const ull*)(Qs + i0 * DIM + d0 + 2);
    const ull q1lo = *(const ull*)(Qs + i1 * DIM + d0);
    const ull q1hi = *(const ull*)(Qs + i1 * DIM + d0 + 2);
    ull r0lo = 0ull, r0hi = 0ull, r1lo = 0ull, r1hi = 0ull;
    ull v0lo = 0ull, v0hi = 0ull, v1lo = 0ull, v1hi = 0ull;

    const float* kr  = Kg + js0 * DIM + d0;
    const float* vr  = Vg + js0 * DIM + d0;
    const float* ea0 = &esA[0][i0][0];
    const float* ea1 = &esA[0][i1][0];

#pragma unroll 4
    for (int j = 0; j < JSPAN; j++) {
        float a0 = ea0[j];                                   // LDS bcast
        float a1 = ea1[j];
        ull a02 = pack2(a0, a0);
        ull a12 = pack2(a1, a1);
        float4 kk4 = *(const float4*)(kr + j * DIM);         // LDG.128
        float4 vv4 = *(const float4*)(vr + j * DIM);
        ull kklo = pack2(kk4.x, kk4.y), kkhi = pack2(kk4.z, kk4.w);
        ull vvlo = pack2(vv4.x, vv4.y), vvhi = pack2(vv4.z, vv4.w);

        r0lo = fma2(relu2(add2(q0lo, kklo)), a02, r0lo);
        r0hi = fma2(relu2(add2(q0hi, kkhi)), a02, r0hi);
        r1lo = fma2(relu2(add2(q1lo, kklo)), a12, r1lo);
        r1hi = fma2(relu2(add2(q1hi, kkhi)), a12, r1hi);
        v0lo = fma2(vvlo, a02, v0lo);
        v0hi = fma2(vvhi, a02, v0hi);
        v1lo = fma2(vvlo, a12, v1lo);
        v1hi = fma2(vvhi, a12, v1hi);
    }

    float x0, y0, x1, y1;
    unpack2(r0lo, x0, y0); unpack2(r0hi, x1, y1);
    *(float4*)&Rpart[sp][ib0 + i0][d0] = make_float4(x0, y0, x1, y1);
    unpack2(r1lo, x0, y0); unpack2(r1hi, x1, y1);
    *(float4*)&Rpart[sp][ib0 + i1][d0] = make_float4(x0, y0, x1, y1);
    unpack2(v0lo, x0, y0); unpack2(v0hi, x1, y1);
    *(float4*)&Vpart[sp][ib0 + i0][d0] = make_float4(x0, y0, x1, y1);
    unpack2(v1lo, x0, y0); unpack2(v1hi, x1, y1);
    *(float4*)&Vpart[sp][ib0 + i1][d0] = make_float4(x0, y0, x1, y1);
}

// ---------------------------------------------------------------------------
// Kernel 3: combine splits + epilogue out = aV + R @ W_Ev + b_Ev
// 8 rows/block; thread = 1 row x 4 cols.
// ---------------------------------------------------------------------------
__global__ __launch_bounds__(256) void combine_kernel(
    const float* __restrict__ WEv,
    const float* __restrict__ bEv,
    float* __restrict__ out)
{
    __shared__ float Rs[8 * DIM];
    const int tid = threadIdx.x;
    const int ib0 = blockIdx.x * 8;
    const int i   = tid >> 5;
    const int c0  = (tid & 31) * 4;
    const int gi  = ib0 + i;

    float m = -1e30f;
#pragma unroll
    for (int p = 0; p < NSPLIT; p++) m = fmaxf(m, Mpart[p][gi]);
    float s = 0.f;
    float4 r = make_float4(0.f, 0.f, 0.f, 0.f);
    float4 v = make_float4(0.f, 0.f, 0.f, 0.f);
#pragma unroll
    for (int p = 0; p < NSPLIT; p++) {
        float c = __expf(Mpart[p][gi] - m);
        s += Spart[p][gi] * c;
        float4 rp = *(const float4*)&Rpart[p][gi][c0];
        float4 vp = *(const float4*)&Vpart[p][gi][c0];
        r.x += c * rp.x;  r.y += c * rp.y;  r.z += c * rp.z;  r.w += c * rp.w;
        v.x += c * vp.x;  v.y += c * vp.y;  v.z += c * vp.z;  v.w += c * vp.w;
    }
    float inv = 1.f / s;
    r.x *= inv;  r.y *= inv;  r.z *= inv;  r.w *= inv;
    v.x *= inv;  v.y *= inv;  v.z *= inv;  v.w *= inv;

    *(float4*)&Rs[i * DIM + c0] = r;
    __syncthreads();

    float4 o = *(const float4*)(bEv + c0);
    o.x += v.x;  o.y += v.y;  o.z += v.z;  o.w += v.w;
    const float* rrow = Rs + i * DIM;
#pragma unroll 8
    for (int dd = 0; dd < DIM; dd++) {
        float4 w = *(const float4*)(WEv + dd * DIM + c0);
        float rv = rrow[dd];                                 // broadcast
        o.x += rv * w.x;  o.y += rv * w.y;
        o.z += rv * w.z;  o.w += rv * w.w;
    }
    *(float4*)(out + gi * DIM + c0) = o;
}

// ---------------------------------------------------------------------------
extern "C" void kernel_launch(void* const* d_in, const int* in_sizes, int n_in,
                              void* d_out, int out_size)
{
    const float* x   = (const float*)d_in[0];
    const float* WQ  = (const float*)d_in[1];
    const float* bQ  = (const float*)d_in[2];
    const float* WK  = (const float*)d_in[3];
    const float* bK  = (const float*)d_in[4];
    const float* WV  = (const float*)d_in[5];
    const float* bV  = (const float*)d_in[6];
    const float* WEv = (const float*)d_in[7];
    const float* bEv = (const float*)d_in[8];
    const float* WA  = (const float*)d_in[9];
    // d_in[10] = b_A: cancels in softmax; unused.
    float* out = (float*)d_out;

    qkv_kernel<<<dim3(256, 3), 128>>>(x, WQ, bQ, WK, bK, WV, bV);
    attn_partial<<<dim3(NTOK / BI, NSPLIT), 256>>>(WA);
    combine_kernel<<<NTOK / 8, 256>>>(WEv, bEv, out);
}

// round 7
// speedup vs baseline: 1.0378x; 1.0378x over previous
#include <cuda_runtime.h>

#define NTOK   1024
#define DIM    128
#define BI     8
#define NSPLIT 4
#define JSPAN  (NTOK / NSPLIT)   // 256

typedef unsigned long long ull;

// ---- packed f32x2 helpers (Blackwell) -------------------------------------
__device__ __forceinline__ ull pack2(float x, float y) {
    ull r; asm("mov.b64 %0, {%1, %2};" : "=l"(r) : "f"(x), "f"(y)); return r;
}
__device__ __forceinline__ void unpack2(ull v, float& x, float& y) {
    asm("mov.b64 {%0, %1}, %2;" : "=f"(x), "=f"(y) : "l"(v));
}
__device__ __forceinline__ ull add2(ull a, ull b) {
    ull r; asm("add.rn.f32x2 %0, %1, %2;" : "=l"(r) : "l"(a), "l"(b)); return r;
}
__device__ __forceinline__ ull fma2(ull a, ull b, ull c) {
    ull r; asm("fma.rn.f32x2 %0, %1, %2, %3;" : "=l"(r) : "l"(a), "l"(b), "l"(c)); return r;
}
__device__ __forceinline__ ull relu2(ull a) {
    float x, y; unpack2(a, x, y);
    return pack2(fmaxf(x, 0.f), fmaxf(y, 0.f));
}

// Scratch (__device__ globals: allocation-free rule)
__device__ float Qg[NTOK * DIM];
__device__ float Kg[NTOK * DIM];
__device__ float Vg[NTOK * DIM];
__device__ float Rpart[NSPLIT][NTOK][DIM];
__device__ float Vpart[NSPLIT][NTOK][DIM];
__device__ float Mpart[NSPLIT][NTOK];
__device__ float Spart[NSPLIT][NTOK];

// ---------------------------------------------------------------------------
// Kernel 1: Q/K/V = x @ W + b. grid (256, 3), 128 thr, 4 rows/block.
// thread = 1 row x 4 cols. Big reg budget -> unroll-8 LDG.128 stays in flight.
// ---------------------------------------------------------------------------
__global__ __launch_bounds__(128, 4) void qkv_kernel(
    const float* __restrict__ x,
    const float* __restrict__ Wq, const float* __restrict__ bq,
    const float* __restrict__ Wk, const float* __restrict__ bk,
    const float* __restrict__ Wv, const float* __restrict__ bv)
{
    __shared__ float xs[4 * DIM];
    const int tid = threadIdx.x;
    const int rt = blockIdx.x;
    const int m  = blockIdx.y;
    const float* W = (m == 0) ? Wq : (m == 1) ? Wk : Wv;
    const float* b = (m == 0) ? bq : (m == 1) ? bk : bv;
    float* outp    = (m == 0) ? Qg : (m == 1) ? Kg : Vg;

    ((float4*)xs)[tid] = ((const float4*)(x + rt * 4 * DIM))[tid];  // 512 floats
    __syncthreads();

    const int row = tid >> 5;
    const int c0  = (tid & 31) * 4;
    float4 acc = *(const float4*)(b + c0);
    const float* xr = xs + row * DIM;

#pragma unroll 8
    for (int d = 0; d < DIM; d++) {
        float4 w = *(const float4*)(W + d * DIM + c0);
        float xv = xr[d];
        acc.x += xv * w.x;  acc.y += xv * w.y;
        acc.z += xv * w.z;  acc.w += xv * w.w;
    }
    *(float4*)(outp + (rt * 4 + row) * DIM + c0) = acc;
}

// ---------------------------------------------------------------------------
// Kernel 2: per-(i-tile, j-split) partial attention.  BI=8, JSPAN=256.
// Phase A as R5; Phase B: thread = 2i x 4d over HALF the j-range + reduction.
// ---------------------------------------------------------------------------
__global__ __launch_bounds__(256) void attn_partial(const float* __restrict__ WA)
{
    __shared__ float es[BI * JSPAN];     // 8 KB
    __shared__ float Qs[BI * DIM];       // 4 KB (row-major, phase B)
    __shared__ float QsT[DIM * BI];      // 4 KB (transposed, phase A)
    __shared__ ull   WAs2[DIM];          // 1 KB ((wa,wa))
    __shared__ ull   red[128 * 8];       // 8 KB (phase B cross-half reduction)

    const int tid = threadIdx.x;
    const int ib0 = blockIdx.x * BI;
    const int sp  = blockIdx.y;
    const int js0 = sp * JSPAN;

    ((float4*)Qs)[tid] = ((const float4*)(Qg + ib0 * DIM))[tid];   // 1024 floats
    for (int k = tid; k < BI * DIM; k += 256)
        QsT[(k & 127) * BI + (k >> 7)] = Qg[ib0 * DIM + k];        // coalesced LDG
    if (tid < DIM) { float w = WA[tid]; WAs2[tid] = pack2(w, w); }
    __syncthreads();

    // ---------------- Phase A: thread owns one j; packed over i-pairs ------
    {
        ull e2[4] = {0ull, 0ull, 0ull, 0ull};   // (e_{2p}, e_{2p+1})
        const float* krow = Kg + (js0 + tid) * DIM;

        for (int db = 0; db < DIM; db += 16) {
            float4 k0 = *(const float4*)(krow + db);
            float4 k1 = *(const float4*)(krow + db + 4);
            float4 k2 = *(const float4*)(krow + db + 8);
            float4 k3 = *(const float4*)(krow + db + 12);
            float kv[16];
            kv[0]=k0.x; kv[1]=k0.y; kv[2]=k0.z; kv[3]=k0.w;
            kv[4]=k1.x; kv[5]=k1.y; kv[6]=k1.z; kv[7]=k1.w;
            kv[8]=k2.x; kv[9]=k2.y; kv[10]=k2.z; kv[11]=k2.w;
            kv[12]=k3.x; kv[13]=k3.y; kv[14]=k3.z; kv[15]=k3.w;
#pragma unroll
            for (int t = 0; t < 16; t++) {
                ull kk2 = pack2(kv[t], kv[t]);           // 1x per d, 4x reuse
                ull wa2 = WAs2[db + t];                  // LDS.64 broadcast
#pragma unroll
                for (int p = 0; p < 4; p++) {
                    ull q2 = *(const ull*)&QsT[(db + t) * BI + 2 * p];  // LDS.64 bcast
                    e2[p] = fma2(relu2(add2(q2, kk2)), wa2, e2[p]);
                }
            }
        }
#pragma unroll
        for (int p = 0; p < 4; p++) {
            float ex, ey; unpack2(e2[p], ex, ey);
            es[(2 * p) * JSPAN + tid]     = ex;
            es[(2 * p + 1) * JSPAN + tid] = ey;
        }
    }
    __syncthreads();

    // ---------------- split-local softmax: warp w -> row w ----------------
    {
        const int w = tid >> 5, lane = tid & 31;
        float* row = es + w * JSPAN;
        float mx = -1e30f;
#pragma unroll
        for (int j = lane; j < JSPAN; j += 32) mx = fmaxf(mx, row[j]);
#pragma unroll
        for (int o = 16; o > 0; o >>= 1) mx = fmaxf(mx, __shfl_xor_sync(0xffffffffu, mx, o));
        float s = 0.f;
#pragma unroll
        for (int j = lane; j < JSPAN; j += 32) {
            float v = __expf(row[j] - mx);
            row[j] = v;                                  // unnormalized p
            s += v;
        }
#pragma unroll
        for (int o = 16; o > 0; o >>= 1) s += __shfl_xor_sync(0xffffffffu, s, o);
        if (lane == 0) {
            Mpart[sp][ib0 + w] = mx;
            Spart[sp][ib0 + w] = s;
        }
    }
    __syncthreads();

    // ---------------- Phase B: thread = 2i x 4d x half-j ------------------
    const int d32 = tid & 31;            // 32 d-positions (x4 floats)
    const int ig  = (tid >> 5) & 3;      // 4 i-groups (warp-uniform)
    const int jh  = tid >> 7;            // 0/1 j-half (warp-uniform)
    const int d0  = d32 * 4;
    const int i0 = ig, i1 = ig + 4;

    const ull q0lo = *(const ull*)(Qs + i0 * DIM + d0);
    const ull q0hi = *(const ull*)(Qs + i0 * DIM + d0 + 2);
    const ull q1lo = *(const ull*)(Qs + i1 * DIM + d0);
    const ull q1hi = *(const ull*)(Qs + i1 * DIM + d0 + 2);
    ull r0lo = 0ull, r0hi = 0ull, r1lo = 0ull, r1hi = 0ull;
    ull v0lo = 0ull, v0hi = 0ull, v1lo = 0ull, v1hi = 0ull;

    const int jbase = jh * (JSPAN / 2);
    const float* kr  = Kg + (js0 + jbase) * DIM + d0;
    const float* vr  = Vg + (js0 + jbase) * DIM + d0;
    const float* ea0 = es + i0 * JSPAN + jbase;
    const float* ea1 = es + i1 * JSPAN + jbase;

#pragma unroll 4
    for (int j = 0; j < JSPAN / 2; j++) {
        float a0 = ea0[j];                               // LDS broadcast
        float a1 = ea1[j];
        ull a02 = pack2(a0, a0);
        ull a12 = pack2(a1, a1);
        float4 kk4 = *(const float4*)(kr + j * DIM);     // LDG.128 (L1-res)
        float4 vv4 = *(const float4*)(vr + j * DIM);
        ull kklo = pack2(kk4.x, kk4.y), kkhi = pack2(kk4.z, kk4.w);
        ull vvlo = pack2(vv4.x, vv4.y), vvhi = pack2(vv4.z, vv4.w);

        r0lo = fma2(relu2(add2(q0lo, kklo)), a02, r0lo);
        r0hi = fma2(relu2(add2(q0hi, kkhi)), a02, r0hi);
        r1lo = fma2(relu2(add2(q1lo, kklo)), a12, r1lo);
        r1hi = fma2(relu2(add2(q1hi, kkhi)), a12, r1hi);
        v0lo = fma2(vvlo, a02, v0lo);
        v0hi = fma2(vvhi, a02, v0hi);
        v1lo = fma2(vvlo, a12, v1lo);
        v1hi = fma2(vvhi, a12, v1hi);
    }

    // cross-half reduction: jh=1 stores, jh=0 adds and writes out
    if (jh == 1) {
        ull* slot = red + (tid & 127) * 8;
        slot[0] = r0lo; slot[1] = r0hi; slot[2] = r1lo; slot[3] = r1hi;
        slot[4] = v0lo; slot[5] = v0hi; slot[6] = v1lo; slot[7] = v1hi;
    }
    __syncthreads();
    if (jh == 0) {
        const ull* slot = red + tid * 8;
        r0lo = add2(r0lo, slot[0]); r0hi = add2(r0hi, slot[1]);
        r1lo = add2(r1lo, slot[2]); r1hi = add2(r1hi, slot[3]);
        v0lo = add2(v0lo, slot[4]); v0hi = add2(v0hi, slot[5]);
        v1lo = add2(v1lo, slot[6]); v1hi = add2(v1hi, slot[7]);

        float x0, y0, x1, y1;
        unpack2(r0lo, x0, y0); unpack2(r0hi, x1, y1);
        *(float4*)&Rpart[sp][ib0 + i0][d0] = make_float4(x0, y0, x1, y1);
        unpack2(r1lo, x0, y0); unpack2(r1hi, x1, y1);
        *(float4*)&Rpart[sp][ib0 + i1][d0] = make_float4(x0, y0, x1, y1);
        unpack2(v0lo, x0, y0); unpack2(v0hi, x1, y1);
        *(float4*)&Vpart[sp][ib0 + i0][d0] = make_float4(x0, y0, x1, y1);
        unpack2(v1lo, x0, y0); unpack2(v1hi, x1, y1);
        *(float4*)&Vpart[sp][ib0 + i1][d0] = make_float4(x0, y0, x1, y1);
    }
}

// ---------------------------------------------------------------------------
// Kernel 3: combine splits + epilogue out = aV + R @ W_Ev + b_Ev
// 8 rows/block; thread = 1 row x 4 cols.
// ---------------------------------------------------------------------------
__global__ __launch_bounds__(256) void combine_kernel(
    const float* __restrict__ WEv,
    const float* __restrict__ bEv,
    float* __restrict__ out)
{
    __shared__ float Rs[BI * DIM];
    const int tid = threadIdx.x;
    const int ib0 = blockIdx.x * BI;
    const int i   = tid >> 5;
    const int c0  = (tid & 31) * 4;
    const int gi  = ib0 + i;

    float m = -1e30f;
#pragma unroll
    for (int p = 0; p < NSPLIT; p++) m = fmaxf(m, Mpart[p][gi]);
    float s = 0.f;
    float4 r = make_float4(0.f, 0.f, 0.f, 0.f);
    float4 v = make_float4(0.f, 0.f, 0.f, 0.f);
#pragma unroll
    for (int p = 0; p < NSPLIT; p++) {
        float c = __expf(Mpart[p][gi] - m);
        s += Spart[p][gi] * c;
        float4 rp = *(const float4*)&Rpart[p][gi][c0];
        float4 vp = *(const float4*)&Vpart[p][gi][c0];
        r.x += c * rp.x;  r.y += c * rp.y;  r.z += c * rp.z;  r.w += c * rp.w;
        v.x += c * vp.x;  v.y += c * vp.y;  v.z += c * vp.z;  v.w += c * vp.w;
    }
    float inv = 1.f / s;
    r.x *= inv;  r.y *= inv;  r.z *= inv;  r.w *= inv;
    v.x *= inv;  v.y *= inv;  v.z *= inv;  v.w *= inv;

    *(float4*)&Rs[i * DIM + c0] = r;
    __syncthreads();

    float4 o = *(const float4*)(bEv + c0);
    o.x += v.x;  o.y += v.y;  o.z += v.z;  o.w += v.w;
    const float* rrow = Rs + i * DIM;
#pragma unroll 8
    for (int dd = 0; dd < DIM; dd++) {
        float4 w = *(const float4*)(WEv + dd * DIM + c0);
        float rv = rrow[dd];                             // broadcast
        o.x += rv * w.x;  o.y += rv * w.y;
        o.z += rv * w.z;  o.w += rv * w.w;
    }
    *(float4*)(out + gi * DIM + c0) = o;
}

// ---------------------------------------------------------------------------
extern "C" void kernel_launch(void* const* d_in, const int* in_sizes, int n_in,
                              void* d_out, int out_size)
{
    const float* x   = (const float*)d_in[0];
    const float* WQ  = (const float*)d_in[1];
    const float* bQ  = (const float*)d_in[2];
    const float* WK  = (const float*)d_in[3];
    const float* bK  = (const float*)d_in[4];
    const float* WV  = (const float*)d_in[5];
    const float* bV  = (const float*)d_in[6];
    const float* WEv = (const float*)d_in[7];
    const float* bEv = (const float*)d_in[8];
    const float* WA  = (const float*)d_in[9];
    // d_in[10] = b_A: cancels in softmax; unused.
    float* out = (float*)d_out;

    qkv_kernel<<<dim3(256, 3), 128>>>(x, WQ, bQ, WK, bK, WV, bV);
    attn_partial<<<dim3(NTOK / BI, NSPLIT), 256>>>(WA);
    combine_kernel<<<NTOK / BI, 256>>>(WEv, bEv, out);
}